// round 13
// baseline (speedup 1.0000x reference)
#include <cuda_runtime.h>
#include <cuda_bf16.h>
#include <cstdint>
#include <math.h>

// Problem constants (fixed by the dataset)
#define Bc 4
#define Tc 2048
#define Dc 1024
#define Hc 16
#define HDc 64
#define BT (Bc*Tc)        // 8192
#define QKV_N (3*Dc)      // 3072

// ---------------------------------------------------------------------------
// Global scratch (no cudaMalloc allowed)
// ---------------------------------------------------------------------------
__device__ float g_qkv[BT * QKV_N];        // (B*T, 3*D) fp32
__device__ __nv_bfloat16 g_xh[BT * Dc];
__device__ __nv_bfloat16 g_xl[BT * Dc];
__device__ __nv_bfloat16 g_wqkv_h[QKV_N * Dc];  // Wqkv^T hi/lo, [3072,1024]
__device__ __nv_bfloat16 g_wqkv_l[QKV_N * Dc];
__device__ __nv_bfloat16 g_wout_h[Dc * Dc];
__device__ __nv_bfloat16 g_wout_l[Dc * Dc];
__device__ __nv_bfloat16 g_ah[BT * Dc];    // attention out hi/lo (A of out proj)
__device__ __nv_bfloat16 g_al[BT * Dc];
// Pre-converted attention operands:
__device__ __nv_bfloat16 g_qh[Bc * Hc * Tc * HDc];   // [B][H][T][64] scaled
__device__ __nv_bfloat16 g_ql[Bc * Hc * Tc * HDc];
__device__ __nv_bfloat16 g_kh[Bc * Hc * Tc * HDc];   // [B][H][T][64]
__device__ __nv_bfloat16 g_kl[Bc * Hc * Tc * HDc];
__device__ __nv_bfloat16 g_vh[Bc * Hc * HDc * Tc];   // [B][H][64][T] transposed
__device__ __nv_bfloat16 g_vl[Bc * Hc * HDc * Tc];

// ---------------------------------------------------------------------------
// PTX helpers (base compute_103: mma.sync + ldmatrix + cp.async)
// ---------------------------------------------------------------------------
__device__ __forceinline__ uint32_t smem_to_u32(const void* p) {
    uint32_t a;
    asm("{ .reg .u64 t; cvta.to.shared.u64 t, %1; cvt.u32.u64 %0, t; }" : "=r"(a) : "l"(p));
    return a;
}

#define CP_ASYNC_16(dst, src) \
    asm volatile("cp.async.cg.shared.global [%0], [%1], 16;" :: "r"(dst), "l"(src))
#define CP_ASYNC_COMMIT() \
    asm volatile("cp.async.commit_group;" ::: "memory")
#define CP_ASYNC_WAIT(n) \
    asm volatile("cp.async.wait_group %0;" :: "n"(n) : "memory")

#define LDSM_X4(r0, r1, r2, r3, addr) \
    asm volatile("ldmatrix.sync.aligned.m8n8.x4.shared.b16 {%0,%1,%2,%3}, [%4];" \
        : "=r"(r0), "=r"(r1), "=r"(r2), "=r"(r3) : "r"(addr))

#define MMA_AB(d, a, b0v, b1v) \
    asm volatile("mma.sync.aligned.m16n8k16.row.col.f32.bf16.bf16.f32 " \
        "{%0,%1,%2,%3}, {%4,%5,%6,%7}, {%8,%9}, {%0,%1,%2,%3};" \
        : "+f"((d)[0]), "+f"((d)[1]), "+f"((d)[2]), "+f"((d)[3]) \
        : "r"((a)[0]), "r"((a)[1]), "r"((a)[2]), "r"((a)[3]), \
          "r"(b0v), "r"(b1v))

__device__ __forceinline__ void split2(float a, float b, uint32_t& hi, uint32_t& lo) {
    __nv_bfloat16 ha = __float2bfloat16(a), hb = __float2bfloat16(b);
    __nv_bfloat162 hh = __halves2bfloat162(ha, hb);
    __nv_bfloat162 ll = __halves2bfloat162(
        __float2bfloat16(a - __bfloat162float(ha)),
        __float2bfloat16(b - __bfloat162float(hb)));
    hi = *(uint32_t*)&hh;
    lo = *(uint32_t*)&ll;
}

// ---------------------------------------------------------------------------
// bf16-split GEMM via mma.sync: C[M,N] = (Ah+Al)[M,K] @ (Bh+Bl)[N,K]^T, fp32.
// CTA tile 128x256, warp tile 64x64 (8 warps: 2 M x 4 N), BK=32,
// double-buffered cp.async, 1 CTA/SM. Fatter warp tile -> 192 MMAs per
// 32 LDSM per chunk (6:1), fewer barriers per MMA.
// ---------------------------------------------------------------------------
#define BKc 32
#define ROWB 80
#define A_TB (128 * ROWB)              // 10240
#define B_TB (256 * ROWB)              // 20480
#define OFF_AL A_TB
#define OFF_BH (2 * A_TB)
#define OFF_BL (2 * A_TB + B_TB)
#define STAGE_SB (2 * A_TB + 2 * B_TB) // 61440
#define MMA_GEMM_SMEM (2 * STAGE_SB)   // 122880

__global__ __launch_bounds__(256, 1) void gemm_mma_kernel(
    const __nv_bfloat16* __restrict__ Ah, const __nv_bfloat16* __restrict__ Al,
    const __nv_bfloat16* __restrict__ Bh, const __nv_bfloat16* __restrict__ Bl,
    float* __restrict__ C, int N, int K)
{
    extern __shared__ __align__(128) char smem[];
    const uint32_t sb = smem_to_u32(smem);
    const int tid  = threadIdx.x;
    const int lane = tid & 31;
    const int wid  = tid >> 5;
    const int wm   = wid & 1;          // 0..1 : 64 rows
    const int wn   = wid >> 1;         // 0..3 : 64 cols
    const int m0 = blockIdx.y * 128;
    const int n0 = blockIdx.x * 256;
    const int nchunk = K / BKc;

    float acc[4][8][4];
    #pragma unroll
    for (int i = 0; i < 4; i++)
        #pragma unroll
        for (int j = 0; j < 8; j++)
            #pragma unroll
            for (int r = 0; r < 4; r++) acc[i][j][r] = 0.f;

    auto load_chunk = [&](int c, int buf) {
        const uint32_t base = sb + buf * STAGE_SB;
        // A hi/lo: 128 rows x 64B (4x16B per row) each
        #pragma unroll
        for (int i = 0; i < 2; i++) {
            int idx = tid + i * 256;
            int r = idx >> 2, q = idx & 3;
            uint32_t off = r * ROWB + q * 16;
            size_t g = (size_t)(m0 + r) * K + c * BKc + q * 8;
            CP_ASYNC_16(base + off,          Ah + g);
            CP_ASYNC_16(base + OFF_AL + off, Al + g);
        }
        // B hi/lo: 256 rows
        #pragma unroll
        for (int i = 0; i < 4; i++) {
            int idx = tid + i * 256;
            int r = idx >> 2, q = idx & 3;
            uint32_t off = r * ROWB + q * 16;
            size_t g = (size_t)(n0 + r) * K + c * BKc + q * 8;
            CP_ASYNC_16(base + OFF_BH + off, Bh + g);
            CP_ASYNC_16(base + OFF_BL + off, Bl + g);
        }
        CP_ASYNC_COMMIT();
    };

    load_chunk(0, 0);

    for (int c = 0; c < nchunk; c++) {
        const int buf = c & 1;
        if (c + 1 < nchunk) {
            load_chunk(c + 1, buf ^ 1);
            CP_ASYNC_WAIT(1);
        } else {
            CP_ASYNC_WAIT(0);
        }
        __syncthreads();

        const uint32_t base = sb + buf * STAGE_SB;

        #pragma unroll
        for (int ks = 0; ks < 2; ks++) {
            // A fragments (hi/lo) for this warp's 64 rows
            uint32_t ah[4][4], al[4][4];
            #pragma unroll
            for (int mf = 0; mf < 4; mf++) {
                int row = wm * 64 + mf * 16 + (lane & 15);
                uint32_t addr = base + row * ROWB + ks * 32 + ((lane >> 4) * 16);
                LDSM_X4(ah[mf][0], ah[mf][1], ah[mf][2], ah[mf][3], addr);
                LDSM_X4(al[mf][0], al[mf][1], al[mf][2], al[mf][3], addr + OFF_AL);
            }
            // B in 4 pair-chunks; 24 MMAs per pair between LDSMs
            #pragma unroll
            for (int p = 0; p < 4; p++) {
                int row = wn * 64 + p * 16 + ((lane >> 4) << 3) + (lane & 7);
                uint32_t addr = base + OFF_BH + row * ROWB
                              + ks * 32 + (((lane >> 3) & 1) * 16);
                uint32_t b0, b1, b2, b3, c0, c1, c2, c3;
                LDSM_X4(b0, b1, b2, b3, addr);
                LDSM_X4(c0, c1, c2, c3, addr + B_TB);
                #pragma unroll
                for (int mf = 0; mf < 4; mf++) {
                    MMA_AB(acc[mf][2*p],   ah[mf], b0, b1);
                    MMA_AB(acc[mf][2*p+1], ah[mf], b2, b3);
                }
                #pragma unroll
                for (int mf = 0; mf < 4; mf++) {
                    MMA_AB(acc[mf][2*p],   ah[mf], c0, c1);
                    MMA_AB(acc[mf][2*p+1], ah[mf], c2, c3);
                }
                #pragma unroll
                for (int mf = 0; mf < 4; mf++) {
                    MMA_AB(acc[mf][2*p],   al[mf], b0, b1);
                    MMA_AB(acc[mf][2*p+1], al[mf], b2, b3);
                }
            }
        }
        __syncthreads();
    }

    #pragma unroll
    for (int mf = 0; mf < 4; mf++) {
        #pragma unroll
        for (int nf = 0; nf < 8; nf++) {
            int row = m0 + wm * 64 + mf * 16 + (lane >> 2);
            int col = n0 + wn * 64 + nf * 8 + (lane & 3) * 2;
            *(float2*)&C[(size_t)row * N + col] =
                make_float2(acc[mf][nf][0], acc[mf][nf][1]);
            *(float2*)&C[(size_t)(row + 8) * N + col] =
                make_float2(acc[mf][nf][2], acc[mf][nf][3]);
        }
    }
}

// ---------------------------------------------------------------------------
// Pre-convert qkv fp32 -> attention bf16 hi/lo layouts.
// ---------------------------------------------------------------------------
__global__ __launch_bounds__(256) void preconvert_kernel(
    const float* __restrict__ qkv)
{
    __shared__ float vt[64][65];
    const int tid = threadIdx.x;
    const int t0  = blockIdx.x * 64;
    const int h   = blockIdx.y;
    const int b   = blockIdx.z;
    const size_t bhT = ((size_t)b * Hc + h) * Tc;
    const int bT = b * Tc;

    for (int i = tid; i < 64 * 64; i += 256) {
        int t = i >> 6, c = i & 63;
        size_t base = (size_t)(bT + t0 + t) * QKV_N + h * HDc + c;
        float qv = qkv[base] * 0.125f;
        float kv = qkv[base + Dc];
        float vv = qkv[base + 2 * Dc];
        size_t o = (bhT + t0 + t) * HDc + c;
        __nv_bfloat16 qhh = __float2bfloat16(qv);
        g_qh[o] = qhh;
        g_ql[o] = __float2bfloat16(qv - __bfloat162float(qhh));
        __nv_bfloat16 khh = __float2bfloat16(kv);
        g_kh[o] = khh;
        g_kl[o] = __float2bfloat16(kv - __bfloat162float(khh));
        vt[t][c] = vv;
    }
    __syncthreads();
    for (int i = tid; i < 64 * 64; i += 256) {
        int c = i >> 6, t = i & 63;
        float vv = vt[t][c];
        __nv_bfloat16 vhh = __float2bfloat16(vv);
        size_t o = (((size_t)b * Hc + h) * HDc + c) * Tc + t0 + t;
        g_vh[o] = vhh;
        g_vl[o] = __float2bfloat16(vv - __bfloat162float(vhh));
    }
}

// ---------------------------------------------------------------------------
// HMMA flash attention (cp.async double-buffered bf16 operands).
// Longest-first q-tile order (LPT scheduling for the causal imbalance).
// ---------------------------------------------------------------------------
#define QHB 0
#define QLB 18432
#define STG0 36864
#define STG_SZ 36864
#define KLOFF 9216
#define VHOFF 18432
#define VLOFF 27648
#define POSB (STG0 + 2*STG_SZ)
#define ATTN_SMEM (POSB + 2*64*4)

__global__ __launch_bounds__(256) void attn_mma_kernel(
    const int* __restrict__ pos,
    __nv_bfloat16* __restrict__ outh,
    __nv_bfloat16* __restrict__ outl)
{
    extern __shared__ __align__(128) char smem[];
    const uint32_t sb = smem_to_u32(smem);
    int* spos = (int*)(smem + POSB);

    const int tid  = threadIdx.x;
    const int lane = tid & 31;
    const int wid  = tid >> 5;

    // Longest blocks (largest q0 => most KV tiles) scheduled first
    const int q0  = ((int)gridDim.x - 1 - (int)blockIdx.x) * 128;
    const int h   = blockIdx.y;
    const int b   = blockIdx.z;
    const int bt0 = b * Tc + q0;
    const int bT  = b * Tc;
    const size_t bhT = ((size_t)b * Hc + h) * Tc;
    const size_t bhV = ((size_t)b * Hc + h) * HDc;

    // Q hi/lo into smem (coalesced 16B)
    for (int i = tid; i < 128 * 8; i += 256) {
        int r = i >> 3, q = i & 7;
        *(uint4*)(smem + QHB + r * 144 + q * 16) =
            *(const uint4*)(g_qh + (bhT + q0 + r) * HDc + q * 8);
        *(uint4*)(smem + QLB + r * 144 + q * 16) =
            *(const uint4*)(g_ql + (bhT + q0 + r) * HDc + q * 8);
    }
    const int pq0 = pos[bt0 + wid * 16 + (lane >> 2)];
    const int pq1 = pos[bt0 + wid * 16 + (lane >> 2) + 8];
    const int pqmax = pos[bt0 + 127];

    auto kv_prefetch = [&](int it, int s) {
        const uint32_t st = sb + STG0 + s * STG_SZ;
        const int k0 = it * 64;
        #pragma unroll
        for (int i = 0; i < 2; i++) {
            int idx = tid + i * 256;
            int j = idx >> 3, q = idx & 7;
            uint32_t d = st + j * 144 + q * 16;
            CP_ASYNC_16(d,         g_kh + (bhT + k0 + j) * HDc + q * 8);
            CP_ASYNC_16(d + KLOFF, g_kl + (bhT + k0 + j) * HDc + q * 8);
            CP_ASYNC_16(d + VHOFF, g_vh + (bhV + j) * Tc + k0 + q * 8);
            CP_ASYNC_16(d + VLOFF, g_vl + (bhV + j) * Tc + k0 + q * 8);
        }
        if (tid < 64) spos[s * 64 + tid] = pos[bT + k0 + tid];
        CP_ASYNC_COMMIT();
    };

    // Issue first KV stage, then scan for tile count while it flies
    kv_prefetch(0, 0);
    int nt = 1;
    while (nt < Tc / 64 && pos[bT + nt * 64] <= pqmax) nt++;

    __syncthreads();

    uint32_t qh[4][4], ql[4][4];
    #pragma unroll
    for (int ks = 0; ks < 4; ks++) {
        uint32_t addr = sb + QHB + (wid * 16 + (lane & 15)) * 144
                      + ks * 32 + (lane >> 4) * 16;
        LDSM_X4(qh[ks][0], qh[ks][1], qh[ks][2], qh[ks][3], addr);
        LDSM_X4(ql[ks][0], ql[ks][1], ql[ks][2], ql[ks][3], addr + (QLB - QHB));
    }

    float m0 = -1e30f, m1 = -1e30f, l0 = 0.f, l1 = 0.f;
    float oacc[8][4];
    #pragma unroll
    for (int nf = 0; nf < 8; nf++)
        #pragma unroll
        for (int r = 0; r < 4; r++) oacc[nf][r] = 0.f;

    for (int it = 0; it < nt; it++) {
        const int buf = it & 1;
        if (it + 1 < nt) {
            kv_prefetch(it + 1, buf ^ 1);
            CP_ASYNC_WAIT(1);
        } else {
            CP_ASYNC_WAIT(0);
        }
        __syncthreads();

        const uint32_t st = sb + STG0 + buf * STG_SZ;

        // S = Q K^T (hi/lo split, fp32 accum)
        float sacc[8][4];
        #pragma unroll
        for (int nf = 0; nf < 8; nf++)
            #pragma unroll
            for (int r = 0; r < 4; r++) sacc[nf][r] = 0.f;

        #pragma unroll
        for (int ks = 0; ks < 4; ks++) {
            #pragma unroll
            for (int p = 0; p < 4; p++) {
                uint32_t row = p * 16 + ((lane >> 4) << 3) + (lane & 7);
                uint32_t addr = st + row * 144 + ks * 32 + (((lane >> 3) & 1) * 16);
                uint32_t h0, h1, h2, h3, lo0, lo1, lo2, lo3;
                LDSM_X4(h0, h1, h2, h3, addr);
                LDSM_X4(lo0, lo1, lo2, lo3, addr + KLOFF);
                MMA_AB(sacc[2*p],   qh[ks], h0, h1);
                MMA_AB(sacc[2*p],   qh[ks], lo0, lo1);
                MMA_AB(sacc[2*p],   ql[ks], h0, h1);
                MMA_AB(sacc[2*p+1], qh[ks], h2, h3);
                MMA_AB(sacc[2*p+1], qh[ks], lo2, lo3);
                MMA_AB(sacc[2*p+1], ql[ks], h2, h3);
            }
        }

        // Mask + online softmax
        const int* sp = spos + buf * 64;
        float mx0 = -1e30f, mx1 = -1e30f;
        #pragma unroll
        for (int nf = 0; nf < 8; nf++) {
            int jc = nf * 8 + (lane & 3) * 2;
            int p0 = sp[jc], p1 = sp[jc + 1];
            if (p0 > pq0) sacc[nf][0] = -1e30f;
            if (p1 > pq0) sacc[nf][1] = -1e30f;
            if (p0 > pq1) sacc[nf][2] = -1e30f;
            if (p1 > pq1) sacc[nf][3] = -1e30f;
            mx0 = fmaxf(mx0, fmaxf(sacc[nf][0], sacc[nf][1]));
            mx1 = fmaxf(mx1, fmaxf(sacc[nf][2], sacc[nf][3]));
        }
        mx0 = fmaxf(mx0, __shfl_xor_sync(0xffffffffu, mx0, 1));
        mx0 = fmaxf(mx0, __shfl_xor_sync(0xffffffffu, mx0, 2));
        mx1 = fmaxf(mx1, __shfl_xor_sync(0xffffffffu, mx1, 1));
        mx1 = fmaxf(mx1, __shfl_xor_sync(0xffffffffu, mx1, 2));

        float mn0 = fmaxf(m0, mx0), mn1 = fmaxf(m1, mx1);
        float al0 = __expf(m0 - mn0), al1 = __expf(m1 - mn1);
        float ps0 = 0.f, ps1 = 0.f;
        #pragma unroll
        for (int nf = 0; nf < 8; nf++) {
            sacc[nf][0] = __expf(sacc[nf][0] - mn0); ps0 += sacc[nf][0];
            sacc[nf][1] = __expf(sacc[nf][1] - mn0); ps0 += sacc[nf][1];
            sacc[nf][2] = __expf(sacc[nf][2] - mn1); ps1 += sacc[nf][2];
            sacc[nf][3] = __expf(sacc[nf][3] - mn1); ps1 += sacc[nf][3];
        }
        ps0 += __shfl_xor_sync(0xffffffffu, ps0, 1);
        ps0 += __shfl_xor_sync(0xffffffffu, ps0, 2);
        ps1 += __shfl_xor_sync(0xffffffffu, ps1, 1);
        ps1 += __shfl_xor_sync(0xffffffffu, ps1, 2);
        l0 = l0 * al0 + ps0;  m0 = mn0;
        l1 = l1 * al1 + ps1;  m1 = mn1;
        #pragma unroll
        for (int nf = 0; nf < 8; nf++) {
            oacc[nf][0] *= al0; oacc[nf][1] *= al0;
            oacc[nf][2] *= al1; oacc[nf][3] *= al1;
        }

        // O += P V
        #pragma unroll
        for (int ksp = 0; ksp < 4; ksp++) {
            uint32_t ph[4], pl[4];
            split2(sacc[2*ksp][0],   sacc[2*ksp][1],   ph[0], pl[0]);
            split2(sacc[2*ksp][2],   sacc[2*ksp][3],   ph[1], pl[1]);
            split2(sacc[2*ksp+1][0], sacc[2*ksp+1][1], ph[2], pl[2]);
            split2(sacc[2*ksp+1][2], sacc[2*ksp+1][3], ph[3], pl[3]);
            #pragma unroll
            for (int p = 0; p < 4; p++) {
                uint32_t row = p * 16 + ((lane >> 4) << 3) + (lane & 7);
                uint32_t addr = st + VHOFF + row * 144
                              + ksp * 32 + (((lane >> 3) & 1) * 16);
                uint32_t v0, v1, v2, v3, w0, w1, w2, w3;
                LDSM_X4(v0, v1, v2, v3, addr);
                LDSM_X4(w0, w1, w2, w3, addr + (VLOFF - VHOFF));
                MMA_AB(oacc[2*p],   ph, v0, v1);
                MMA_AB(oacc[2*p],   ph, w0, w1);
                MMA_AB(oacc[2*p],   pl, v0, v1);
                MMA_AB(oacc[2*p+1], ph, v2, v3);
                MMA_AB(oacc[2*p+1], ph, w2, w3);
                MMA_AB(oacc[2*p+1], pl, v2, v3);
            }
        }
        __syncthreads();
    }

    // Epilogue: normalize + fused bf16 hi/lo split for the out-projection
    const float inv0 = 1.0f / l0;
    const float inv1 = 1.0f / l1;
    const int r0 = bt0 + wid * 16 + (lane >> 2);
    const int r1 = r0 + 8;
    #pragma unroll
    for (int nf = 0; nf < 8; nf++) {
        int col = h * HDc + nf * 8 + (lane & 3) * 2;
        uint32_t hi, lo;
        split2(oacc[nf][0] * inv0, oacc[nf][1] * inv0, hi, lo);
        *(uint32_t*)&outh[(size_t)r0 * Dc + col] = hi;
        *(uint32_t*)&outl[(size_t)r0 * Dc + col] = lo;
        split2(oacc[nf][2] * inv1, oacc[nf][3] * inv1, hi, lo);
        *(uint32_t*)&outh[(size_t)r1 * Dc + col] = hi;
        *(uint32_t*)&outl[(size_t)r1 * Dc + col] = lo;
    }
}

// ---------------------------------------------------------------------------
// fp32 -> bf16 hi/lo split (vectorized x4)
// ---------------------------------------------------------------------------
__global__ __launch_bounds__(256) void split_kernel(
    const float4* __restrict__ in, __nv_bfloat162* __restrict__ hi,
    __nv_bfloat162* __restrict__ lo, int n4)
{
    int i = blockIdx.x * blockDim.x + threadIdx.x;
    if (i >= n4) return;
    float4 v = in[i];
    __nv_bfloat16 h0 = __float2bfloat16(v.x);
    __nv_bfloat16 h1 = __float2bfloat16(v.y);
    __nv_bfloat16 h2 = __float2bfloat16(v.z);
    __nv_bfloat16 h3 = __float2bfloat16(v.w);
    hi[2*i]   = __halves2bfloat162(h0, h1);
    hi[2*i+1] = __halves2bfloat162(h2, h3);
    lo[2*i]   = __halves2bfloat162(__float2bfloat16(v.x - __bfloat162float(h0)),
                                   __float2bfloat16(v.y - __bfloat162float(h1)));
    lo[2*i+1] = __halves2bfloat162(__float2bfloat16(v.z - __bfloat162float(h2)),
                                   __float2bfloat16(v.w - __bfloat162float(h3)));
}

// ---------------------------------------------------------------------------
// Both weight transposes in ONE launch: W [K,N] fp32 -> W^T [N,K] bf16 hi/lo.
// blockIdx.x < 96 -> Wqkv (N=3072); else -> Wout (N=1024).
// ---------------------------------------------------------------------------
__global__ __launch_bounds__(256) void transpose_split_both_kernel(
    const float* __restrict__ Wqkv, const float* __restrict__ Wout)
{
    __shared__ float t[32][33];
    const int tx = threadIdx.x;
    const int ty = threadIdx.y;
    const bool is_qkv = (blockIdx.x < 96);
    const float* in = is_qkv ? Wqkv : Wout;
    __nv_bfloat16* hiT = is_qkv ? g_wqkv_h : g_wout_h;
    __nv_bfloat16* loT = is_qkv ? g_wqkv_l : g_wout_l;
    const int N = is_qkv ? QKV_N : Dc;
    const int n0 = (is_qkv ? blockIdx.x : (blockIdx.x - 96)) * 32;
    const int k0 = blockIdx.y * 32;
    const int K = Dc;

    #pragma unroll
    for (int i = 0; i < 4; i++) {
        int row = ty + i * 8;
        t[row][tx] = in[(size_t)(k0 + row) * N + n0 + tx];
    }
    __syncthreads();
    #pragma unroll
    for (int i = 0; i < 4; i++) {
        int row = ty + i * 8;
        float v = t[tx][row];
        __nv_bfloat16 h = __float2bfloat16(v);
        size_t o = (size_t)(n0 + row) * K + k0 + tx;
        hiT[o] = h;
        loT[o] = __float2bfloat16(v - __bfloat162float(h));
    }
}

// ---------------------------------------------------------------------------
extern "C" void kernel_launch(void* const* d_in, const int* in_sizes, int n_in,
                              void* d_out, int out_size)
{
    const float* x    = (const float*)d_in[0];
    const int*   pos  = (const int*)  d_in[1];
    const float* Wqkv = (const float*)d_in[2];
    const float* Wout = (const float*)d_in[3];
    float* out = (float*)d_out;

    float *qkv_ptr = nullptr;
    __nv_bfloat16 *xh, *xl, *wqh, *wql, *woh, *wol, *ah, *al;
    cudaGetSymbolAddress((void**)&qkv_ptr,  g_qkv);
    cudaGetSymbolAddress((void**)&xh,  g_xh);
    cudaGetSymbolAddress((void**)&xl,  g_xl);
    cudaGetSymbolAddress((void**)&wqh, g_wqkv_h);
    cudaGetSymbolAddress((void**)&wql, g_wqkv_l);
    cudaGetSymbolAddress((void**)&woh, g_wout_h);
    cudaGetSymbolAddress((void**)&wol, g_wout_l);
    cudaGetSymbolAddress((void**)&ah,  g_ah);
    cudaGetSymbolAddress((void**)&al,  g_al);

    static bool attr_set = false;
    if (!attr_set) {
        cudaFuncSetAttribute(gemm_mma_kernel,
                             cudaFuncAttributeMaxDynamicSharedMemorySize, MMA_GEMM_SMEM);
        cudaFuncSetAttribute(attn_mma_kernel,
                             cudaFuncAttributeMaxDynamicSharedMemorySize, ATTN_SMEM);
        attr_set = true;
    }

    // 0) Input splits (x) + both weight transposes (single launch)
    {
        int n4 = BT * Dc / 4;
        split_kernel<<<(n4 + 255) / 256, 256>>>(
            (const float4*)x, (__nv_bfloat162*)xh, (__nv_bfloat162*)xl, n4);
    }
    {
        dim3 grid(96 + 32, 32);
        transpose_split_both_kernel<<<grid, dim3(32, 8)>>>(Wqkv, Wout);
    }

    // 1) QKV projection on HMMA: (8192,1024) @ (1024,3072), 128x256 tiles
    {
        dim3 grid(QKV_N / 256, BT / 128);
        gemm_mma_kernel<<<grid, 256, MMA_GEMM_SMEM>>>(
            xh, xl, wqh, wql, qkv_ptr, QKV_N, Dc);
    }

    // 2) Pre-convert Q/K/V to bf16 hi/lo attention layouts (V transposed)
    {
        dim3 grid(Tc / 64, Hc, Bc);
        preconvert_kernel<<<grid, 256>>>(qkv_ptr);
    }

    // 3) Attention on HMMA (longest-first order, fused output split)
    {
        dim3 grid(Tc / 128, Hc, Bc);
        attn_mma_kernel<<<grid, 256, ATTN_SMEM>>>(pos, ah, al);
    }

    // 4) Out projection on HMMA: (8192,1024) @ (1024,1024), 128x256 tiles
    {
        dim3 grid(Dc / 256, BT / 128);
        gemm_mma_kernel<<<grid, 256, MMA_GEMM_SMEM>>>(
            ah, al, woh, wol, out, Dc, Dc);
    }
}

// round 14
// speedup vs baseline: 1.0724x; 1.0724x over previous
#include <cuda_runtime.h>
#include <cuda_bf16.h>
#include <cstdint>
#include <math.h>

// Problem constants (fixed by the dataset)
#define Bc 4
#define Tc 2048
#define Dc 1024
#define Hc 16
#define HDc 64
#define BT (Bc*Tc)        // 8192
#define QKV_N (3*Dc)      // 3072

// ---------------------------------------------------------------------------
// Global scratch (no cudaMalloc allowed)
// ---------------------------------------------------------------------------
__device__ float g_qkv[BT * QKV_N];        // (B*T, 3*D) fp32
__device__ __nv_bfloat16 g_xh[BT * Dc];
__device__ __nv_bfloat16 g_xl[BT * Dc];
__device__ __nv_bfloat16 g_wqkv_h[QKV_N * Dc];  // Wqkv^T hi/lo, [3072,1024]
__device__ __nv_bfloat16 g_wqkv_l[QKV_N * Dc];
__device__ __nv_bfloat16 g_wout_h[Dc * Dc];
__device__ __nv_bfloat16 g_wout_l[Dc * Dc];
__device__ __nv_bfloat16 g_ah[BT * Dc];    // attention out hi/lo (A of out proj)
__device__ __nv_bfloat16 g_al[BT * Dc];
// Pre-converted attention operands:
__device__ __nv_bfloat16 g_qh[Bc * Hc * Tc * HDc];   // [B][H][T][64] scaled
__device__ __nv_bfloat16 g_ql[Bc * Hc * Tc * HDc];
__device__ __nv_bfloat16 g_kh[Bc * Hc * Tc * HDc];   // [B][H][T][64]
__device__ __nv_bfloat16 g_kl[Bc * Hc * Tc * HDc];
__device__ __nv_bfloat16 g_vh[Bc * Hc * HDc * Tc];   // [B][H][64][T] transposed
__device__ __nv_bfloat16 g_vl[Bc * Hc * HDc * Tc];

// ---------------------------------------------------------------------------
// PTX helpers (base compute_103: mma.sync + ldmatrix + cp.async)
// ---------------------------------------------------------------------------
__device__ __forceinline__ uint32_t smem_to_u32(const void* p) {
    uint32_t a;
    asm("{ .reg .u64 t; cvta.to.shared.u64 t, %1; cvt.u32.u64 %0, t; }" : "=r"(a) : "l"(p));
    return a;
}

#define CP_ASYNC_16(dst, src) \
    asm volatile("cp.async.cg.shared.global [%0], [%1], 16;" :: "r"(dst), "l"(src))
#define CP_ASYNC_COMMIT() \
    asm volatile("cp.async.commit_group;" ::: "memory")
#define CP_ASYNC_WAIT(n) \
    asm volatile("cp.async.wait_group %0;" :: "n"(n) : "memory")

#define LDSM_X4(r0, r1, r2, r3, addr) \
    asm volatile("ldmatrix.sync.aligned.m8n8.x4.shared.b16 {%0,%1,%2,%3}, [%4];" \
        : "=r"(r0), "=r"(r1), "=r"(r2), "=r"(r3) : "r"(addr))

#define MMA_BF16(d, a, b) \
    asm volatile("mma.sync.aligned.m16n8k16.row.col.f32.bf16.bf16.f32 " \
        "{%0,%1,%2,%3}, {%4,%5,%6,%7}, {%8,%9}, {%0,%1,%2,%3};" \
        : "+f"((d)[0]), "+f"((d)[1]), "+f"((d)[2]), "+f"((d)[3]) \
        : "r"((a)[0]), "r"((a)[1]), "r"((a)[2]), "r"((a)[3]), \
          "r"((b)[0]), "r"((b)[1]))

#define MMA_AB(d, a, b0v, b1v) \
    asm volatile("mma.sync.aligned.m16n8k16.row.col.f32.bf16.bf16.f32 " \
        "{%0,%1,%2,%3}, {%4,%5,%6,%7}, {%8,%9}, {%0,%1,%2,%3};" \
        : "+f"((d)[0]), "+f"((d)[1]), "+f"((d)[2]), "+f"((d)[3]) \
        : "r"((a)[0]), "r"((a)[1]), "r"((a)[2]), "r"((a)[3]), \
          "r"(b0v), "r"(b1v))

__device__ __forceinline__ void split2(float a, float b, uint32_t& hi, uint32_t& lo) {
    __nv_bfloat16 ha = __float2bfloat16(a), hb = __float2bfloat16(b);
    __nv_bfloat162 hh = __halves2bfloat162(ha, hb);
    __nv_bfloat162 ll = __halves2bfloat162(
        __float2bfloat16(a - __bfloat162float(ha)),
        __float2bfloat16(b - __bfloat162float(hb)));
    hi = *(uint32_t*)&hh;
    lo = *(uint32_t*)&ll;
}

// ---------------------------------------------------------------------------
// bf16-split GEMM via mma.sync — PROVEN round-9 config: 128x128 tile,
// 2 CTAs/SM, BK=32, double-buffered cp.async. (Fat-tile variant regressed:
// losing the second resident CTA cost more than the MMA:LDSM ratio gained.)
// ---------------------------------------------------------------------------
#define BKc 32
#define ROWB 80
#define TILE_SB (128 * ROWB)
#define STAGE_SB (4 * TILE_SB)
#define MMA_GEMM_SMEM (2 * STAGE_SB)

__global__ __launch_bounds__(256, 2) void gemm_mma_kernel(
    const __nv_bfloat16* __restrict__ Ah, const __nv_bfloat16* __restrict__ Al,
    const __nv_bfloat16* __restrict__ Bh, const __nv_bfloat16* __restrict__ Bl,
    float* __restrict__ C, int N, int K)
{
    extern __shared__ __align__(128) char smem[];
    const uint32_t sb = smem_to_u32(smem);
    const int tid  = threadIdx.x;
    const int lane = tid & 31;
    const int wid  = tid >> 5;
    const int wm   = wid & 1;
    const int wn   = wid >> 1;
    const int m0 = blockIdx.y * 128;
    const int n0 = blockIdx.x * 128;
    const int nchunk = K / BKc;

    float acc[4][4][4];
    #pragma unroll
    for (int i = 0; i < 4; i++)
        #pragma unroll
        for (int j = 0; j < 4; j++)
            #pragma unroll
            for (int r = 0; r < 4; r++) acc[i][j][r] = 0.f;

    const __nv_bfloat16* srcs[4] = {Ah, Al, Bh, Bl};

    auto load_chunk = [&](int c, int buf) {
        #pragma unroll
        for (int t = 0; t < 4; t++) {
            const __nv_bfloat16* src = srcs[t];
            const int rbase = (t < 2) ? m0 : n0;
            #pragma unroll
            for (int i = 0; i < 2; i++) {
                int idx = tid + i * 256;
                int r = idx >> 2;
                int q = idx & 3;
                uint32_t dst = sb + buf * STAGE_SB + t * TILE_SB + r * ROWB + q * 16;
                const void* g = src + (size_t)(rbase + r) * K + c * BKc + q * 8;
                CP_ASYNC_16(dst, g);
            }
        }
        CP_ASYNC_COMMIT();
    };

    load_chunk(0, 0);

    for (int c = 0; c < nchunk; c++) {
        const int buf = c & 1;
        if (c + 1 < nchunk) {
            load_chunk(c + 1, buf ^ 1);
            CP_ASYNC_WAIT(1);
        } else {
            CP_ASYNC_WAIT(0);
        }
        __syncthreads();

        const uint32_t a_base = sb + buf * STAGE_SB;
        const uint32_t b_base = a_base + 2 * TILE_SB;

        #pragma unroll
        for (int ks = 0; ks < 2; ks++) {
            uint32_t ah[4][4], al[4][4];
            #pragma unroll
            for (int mf = 0; mf < 4; mf++) {
                int row = wm * 64 + mf * 16 + (lane & 15);
                uint32_t col = ks * 32 + ((lane >> 4) * 16);
                uint32_t addr = a_base + row * ROWB + col;
                LDSM_X4(ah[mf][0], ah[mf][1], ah[mf][2], ah[mf][3], addr);
                LDSM_X4(al[mf][0], al[mf][1], al[mf][2], al[mf][3], addr + TILE_SB);
            }
            uint32_t bh[4][2], bl[4][2];
            #pragma unroll
            for (int p = 0; p < 2; p++) {
                int row = wn * 32 + p * 16 + ((lane >> 4) << 3) + (lane & 7);
                uint32_t col = ks * 32 + (((lane >> 3) & 1) * 16);
                uint32_t addr = b_base + row * ROWB + col;
                LDSM_X4(bh[2*p][0], bh[2*p][1], bh[2*p+1][0], bh[2*p+1][1], addr);
                LDSM_X4(bl[2*p][0], bl[2*p][1], bl[2*p+1][0], bl[2*p+1][1], addr + TILE_SB);
            }
            #pragma unroll
            for (int mf = 0; mf < 4; mf++)
                #pragma unroll
                for (int nf = 0; nf < 4; nf++)
                    MMA_BF16(acc[mf][nf], ah[mf], bh[nf]);
            #pragma unroll
            for (int mf = 0; mf < 4; mf++)
                #pragma unroll
                for (int nf = 0; nf < 4; nf++)
                    MMA_BF16(acc[mf][nf], ah[mf], bl[nf]);
            #pragma unroll
            for (int mf = 0; mf < 4; mf++)
                #pragma unroll
                for (int nf = 0; nf < 4; nf++)
                    MMA_BF16(acc[mf][nf], al[mf], bh[nf]);
        }
        __syncthreads();
    }

    #pragma unroll
    for (int mf = 0; mf < 4; mf++) {
        #pragma unroll
        for (int nf = 0; nf < 4; nf++) {
            int row = m0 + wm * 64 + mf * 16 + (lane >> 2);
            int col = n0 + wn * 32 + nf * 8 + (lane & 3) * 2;
            *(float2*)&C[(size_t)row * N + col] =
                make_float2(acc[mf][nf][0], acc[mf][nf][1]);
            *(float2*)&C[(size_t)(row + 8) * N + col] =
                make_float2(acc[mf][nf][2], acc[mf][nf][3]);
        }
    }
}

// ---------------------------------------------------------------------------
// Pre-convert qkv fp32 -> attention bf16 hi/lo layouts.
// ---------------------------------------------------------------------------
__global__ __launch_bounds__(256) void preconvert_kernel(
    const float* __restrict__ qkv)
{
    __shared__ float vt[64][65];
    const int tid = threadIdx.x;
    const int t0  = blockIdx.x * 64;
    const int h   = blockIdx.y;
    const int b   = blockIdx.z;
    const size_t bhT = ((size_t)b * Hc + h) * Tc;
    const int bT = b * Tc;

    for (int i = tid; i < 64 * 64; i += 256) {
        int t = i >> 6, c = i & 63;
        size_t base = (size_t)(bT + t0 + t) * QKV_N + h * HDc + c;
        float qv = qkv[base] * 0.125f;
        float kv = qkv[base + Dc];
        float vv = qkv[base + 2 * Dc];
        size_t o = (bhT + t0 + t) * HDc + c;
        __nv_bfloat16 qhh = __float2bfloat16(qv);
        g_qh[o] = qhh;
        g_ql[o] = __float2bfloat16(qv - __bfloat162float(qhh));
        __nv_bfloat16 khh = __float2bfloat16(kv);
        g_kh[o] = khh;
        g_kl[o] = __float2bfloat16(kv - __bfloat162float(khh));
        vt[t][c] = vv;
    }
    __syncthreads();
    for (int i = tid; i < 64 * 64; i += 256) {
        int c = i >> 6, t = i & 63;
        float vv = vt[t][c];
        __nv_bfloat16 vhh = __float2bfloat16(vv);
        size_t o = (((size_t)b * Hc + h) * HDc + c) * Tc + t0 + t;
        g_vh[o] = vhh;
        g_vl[o] = __float2bfloat16(vv - __bfloat162float(vhh));
    }
}

// ---------------------------------------------------------------------------
// HMMA flash attention, KV tile = 128 tokens (halves softmax/barrier/prefetch
// overhead per token vs 64). cp.async double-buffered. LPT q-tile order.
// smem: Q hi/lo 128x144B; 2 stages of {Kh,Kl: 128x144B, VhT,VlT: 64x272B}; pos.
// ---------------------------------------------------------------------------
#define TKV 128
#define QHB 0
#define QLB 18432
#define STG0 36864
#define KL_OFF 18432
#define VH_OFF 36864
#define VL_OFF 54272
#define STG_SZ 71680
#define VROWB 272
#define POSB (STG0 + 2*STG_SZ)          // 180224
#define ATTN_SMEM (POSB + 2*TKV*4)      // 181248

__global__ __launch_bounds__(256) void attn_mma_kernel(
    const int* __restrict__ pos,
    __nv_bfloat16* __restrict__ outh,
    __nv_bfloat16* __restrict__ outl)
{
    extern __shared__ __align__(128) char smem[];
    const uint32_t sb = smem_to_u32(smem);
    int* spos = (int*)(smem + POSB);

    const int tid  = threadIdx.x;
    const int lane = tid & 31;
    const int wid  = tid >> 5;

    // Longest blocks (largest q0 => most KV tiles) first
    const int q0  = ((int)gridDim.x - 1 - (int)blockIdx.x) * 128;
    const int h   = blockIdx.y;
    const int b   = blockIdx.z;
    const int bt0 = b * Tc + q0;
    const int bT  = b * Tc;
    const size_t bhT = ((size_t)b * Hc + h) * Tc;
    const size_t bhV = ((size_t)b * Hc + h) * HDc;

    // Q hi/lo into smem (coalesced 16B)
    for (int i = tid; i < 128 * 8; i += 256) {
        int r = i >> 3, q = i & 7;
        *(uint4*)(smem + QHB + r * 144 + q * 16) =
            *(const uint4*)(g_qh + (bhT + q0 + r) * HDc + q * 8);
        *(uint4*)(smem + QLB + r * 144 + q * 16) =
            *(const uint4*)(g_ql + (bhT + q0 + r) * HDc + q * 8);
    }
    const int pq0 = pos[bt0 + wid * 16 + (lane >> 2)];
    const int pq1 = pos[bt0 + wid * 16 + (lane >> 2) + 8];
    const int pqmax = pos[bt0 + 127];

    auto kv_prefetch = [&](int it, int s) {
        const uint32_t st = sb + STG0 + s * STG_SZ;
        const int k0 = it * TKV;
        // K hi/lo: 128 rows x 64 d (8 x 16B per row)
        #pragma unroll
        for (int i = 0; i < 4; i++) {
            int idx = tid + i * 256;          // 0..1023
            int j = idx >> 3, q = idx & 7;
            uint32_t d = st + j * 144 + q * 16;
            CP_ASYNC_16(d,          g_kh + (bhT + k0 + j) * HDc + q * 8);
            CP_ASYNC_16(d + KL_OFF, g_kl + (bhT + k0 + j) * HDc + q * 8);
        }
        // V^T hi/lo: 64 rows x 128 t (16 x 16B per row)
        #pragma unroll
        for (int i = 0; i < 4; i++) {
            int idx = tid + i * 256;          // 0..1023
            int j = idx >> 4, q = idx & 15;
            uint32_t d = st + VH_OFF + j * VROWB + q * 16;
            CP_ASYNC_16(d,                    g_vh + (bhV + j) * Tc + k0 + q * 8);
            CP_ASYNC_16(d + (VL_OFF - VH_OFF), g_vl + (bhV + j) * Tc + k0 + q * 8);
        }
        if (tid < TKV) spos[s * TKV + tid] = pos[bT + k0 + tid];
        CP_ASYNC_COMMIT();
    };

    // First stage in flight while scanning tile count
    kv_prefetch(0, 0);
    int nt = 1;
    while (nt < Tc / TKV && pos[bT + nt * TKV] <= pqmax) nt++;

    __syncthreads();

    uint32_t qh[4][4], ql[4][4];
    #pragma unroll
    for (int ks = 0; ks < 4; ks++) {
        uint32_t addr = sb + QHB + (wid * 16 + (lane & 15)) * 144
                      + ks * 32 + (lane >> 4) * 16;
        LDSM_X4(qh[ks][0], qh[ks][1], qh[ks][2], qh[ks][3], addr);
        LDSM_X4(ql[ks][0], ql[ks][1], ql[ks][2], ql[ks][3], addr + (QLB - QHB));
    }

    float m0 = -1e30f, m1 = -1e30f, l0 = 0.f, l1 = 0.f;
    float oacc[8][4];
    #pragma unroll
    for (int nf = 0; nf < 8; nf++)
        #pragma unroll
        for (int r = 0; r < 4; r++) oacc[nf][r] = 0.f;

    for (int it = 0; it < nt; it++) {
        const int buf = it & 1;
        if (it + 1 < nt) {
            kv_prefetch(it + 1, buf ^ 1);
            CP_ASYNC_WAIT(1);
        } else {
            CP_ASYNC_WAIT(0);
        }
        __syncthreads();

        const uint32_t st = sb + STG0 + buf * STG_SZ;

        // S = Q K^T : 16 n-frags (128 tokens) x 4 k-steps (d=64)
        float sacc[16][4];
        #pragma unroll
        for (int nf = 0; nf < 16; nf++)
            #pragma unroll
            for (int r = 0; r < 4; r++) sacc[nf][r] = 0.f;

        #pragma unroll
        for (int ks = 0; ks < 4; ks++) {
            #pragma unroll
            for (int p = 0; p < 8; p++) {
                uint32_t row = p * 16 + ((lane >> 4) << 3) + (lane & 7);
                uint32_t addr = st + row * 144 + ks * 32 + (((lane >> 3) & 1) * 16);
                uint32_t h0, h1, h2, h3, lo0, lo1, lo2, lo3;
                LDSM_X4(h0, h1, h2, h3, addr);
                LDSM_X4(lo0, lo1, lo2, lo3, addr + KL_OFF);
                MMA_AB(sacc[2*p],   qh[ks], h0, h1);
                MMA_AB(sacc[2*p],   qh[ks], lo0, lo1);
                MMA_AB(sacc[2*p],   ql[ks], h0, h1);
                MMA_AB(sacc[2*p+1], qh[ks], h2, h3);
                MMA_AB(sacc[2*p+1], qh[ks], lo2, lo3);
                MMA_AB(sacc[2*p+1], ql[ks], h2, h3);
            }
        }

        // Mask + online softmax (one pass per 128 tokens)
        const int* sp = spos + buf * TKV;
        float mx0 = -1e30f, mx1 = -1e30f;
        #pragma unroll
        for (int nf = 0; nf < 16; nf++) {
            int jc = nf * 8 + (lane & 3) * 2;
            int p0 = sp[jc], p1 = sp[jc + 1];
            if (p0 > pq0) sacc[nf][0] = -1e30f;
            if (p1 > pq0) sacc[nf][1] = -1e30f;
            if (p0 > pq1) sacc[nf][2] = -1e30f;
            if (p1 > pq1) sacc[nf][3] = -1e30f;
            mx0 = fmaxf(mx0, fmaxf(sacc[nf][0], sacc[nf][1]));
            mx1 = fmaxf(mx1, fmaxf(sacc[nf][2], sacc[nf][3]));
        }
        mx0 = fmaxf(mx0, __shfl_xor_sync(0xffffffffu, mx0, 1));
        mx0 = fmaxf(mx0, __shfl_xor_sync(0xffffffffu, mx0, 2));
        mx1 = fmaxf(mx1, __shfl_xor_sync(0xffffffffu, mx1, 1));
        mx1 = fmaxf(mx1, __shfl_xor_sync(0xffffffffu, mx1, 2));

        float mn0 = fmaxf(m0, mx0), mn1 = fmaxf(m1, mx1);
        float al0 = __expf(m0 - mn0), al1 = __expf(m1 - mn1);
        float ps0 = 0.f, ps1 = 0.f;
        #pragma unroll
        for (int nf = 0; nf < 16; nf++) {
            sacc[nf][0] = __expf(sacc[nf][0] - mn0); ps0 += sacc[nf][0];
            sacc[nf][1] = __expf(sacc[nf][1] - mn0); ps0 += sacc[nf][1];
            sacc[nf][2] = __expf(sacc[nf][2] - mn1); ps1 += sacc[nf][2];
            sacc[nf][3] = __expf(sacc[nf][3] - mn1); ps1 += sacc[nf][3];
        }
        ps0 += __shfl_xor_sync(0xffffffffu, ps0, 1);
        ps0 += __shfl_xor_sync(0xffffffffu, ps0, 2);
        ps1 += __shfl_xor_sync(0xffffffffu, ps1, 1);
        ps1 += __shfl_xor_sync(0xffffffffu, ps1, 2);
        l0 = l0 * al0 + ps0;  m0 = mn0;
        l1 = l1 * al1 + ps1;  m1 = mn1;
        #pragma unroll
        for (int nf = 0; nf < 8; nf++) {
            oacc[nf][0] *= al0; oacc[nf][1] *= al0;
            oacc[nf][2] *= al1; oacc[nf][3] *= al1;
        }

        // O += P V : 8 k-steps of 16 tokens
        #pragma unroll
        for (int ksp = 0; ksp < 8; ksp++) {
            uint32_t ph[4], pl[4];
            split2(sacc[2*ksp][0],   sacc[2*ksp][1],   ph[0], pl[0]);
            split2(sacc[2*ksp][2],   sacc[2*ksp][3],   ph[1], pl[1]);
            split2(sacc[2*ksp+1][0], sacc[2*ksp+1][1], ph[2], pl[2]);
            split2(sacc[2*ksp+1][2], sacc[2*ksp+1][3], ph[3], pl[3]);
            #pragma unroll
            for (int p = 0; p < 4; p++) {
                uint32_t row = p * 16 + ((lane >> 4) << 3) + (lane & 7);
                uint32_t addr = st + VH_OFF + row * VROWB
                              + ksp * 32 + (((lane >> 3) & 1) * 16);
                uint32_t v0, v1, v2, v3, w0, w1, w2, w3;
                LDSM_X4(v0, v1, v2, v3, addr);
                LDSM_X4(w0, w1, w2, w3, addr + (VL_OFF - VH_OFF));
                MMA_AB(oacc[2*p],   ph, v0, v1);
                MMA_AB(oacc[2*p],   ph, w0, w1);
                MMA_AB(oacc[2*p],   pl, v0, v1);
                MMA_AB(oacc[2*p+1], ph, v2, v3);
                MMA_AB(oacc[2*p+1], ph, w2, w3);
                MMA_AB(oacc[2*p+1], pl, v2, v3);
            }
        }
        __syncthreads();
    }

    // Epilogue: normalize + fused bf16 hi/lo split for the out-projection
    const float inv0 = 1.0f / l0;
    const float inv1 = 1.0f / l1;
    const int r0 = bt0 + wid * 16 + (lane >> 2);
    const int r1 = r0 + 8;
    #pragma unroll
    for (int nf = 0; nf < 8; nf++) {
        int col = h * HDc + nf * 8 + (lane & 3) * 2;
        uint32_t hi, lo;
        split2(oacc[nf][0] * inv0, oacc[nf][1] * inv0, hi, lo);
        *(uint32_t*)&outh[(size_t)r0 * Dc + col] = hi;
        *(uint32_t*)&outl[(size_t)r0 * Dc + col] = lo;
        split2(oacc[nf][2] * inv1, oacc[nf][3] * inv1, hi, lo);
        *(uint32_t*)&outh[(size_t)r1 * Dc + col] = hi;
        *(uint32_t*)&outl[(size_t)r1 * Dc + col] = lo;
    }
}

// ---------------------------------------------------------------------------
// fp32 -> bf16 hi/lo split (vectorized x4)
// ---------------------------------------------------------------------------
__global__ __launch_bounds__(256) void split_kernel(
    const float4* __restrict__ in, __nv_bfloat162* __restrict__ hi,
    __nv_bfloat162* __restrict__ lo, int n4)
{
    int i = blockIdx.x * blockDim.x + threadIdx.x;
    if (i >= n4) return;
    float4 v = in[i];
    __nv_bfloat16 h0 = __float2bfloat16(v.x);
    __nv_bfloat16 h1 = __float2bfloat16(v.y);
    __nv_bfloat16 h2 = __float2bfloat16(v.z);
    __nv_bfloat16 h3 = __float2bfloat16(v.w);
    hi[2*i]   = __halves2bfloat162(h0, h1);
    hi[2*i+1] = __halves2bfloat162(h2, h3);
    lo[2*i]   = __halves2bfloat162(__float2bfloat16(v.x - __bfloat162float(h0)),
                                   __float2bfloat16(v.y - __bfloat162float(h1)));
    lo[2*i+1] = __halves2bfloat162(__float2bfloat16(v.z - __bfloat162float(h2)),
                                   __float2bfloat16(v.w - __bfloat162float(h3)));
}

// ---------------------------------------------------------------------------
// Both weight transposes in ONE launch: W [K,N] fp32 -> W^T [N,K] bf16 hi/lo.
// ---------------------------------------------------------------------------
__global__ __launch_bounds__(256) void transpose_split_both_kernel(
    const float* __restrict__ Wqkv, const float* __restrict__ Wout)
{
    __shared__ float t[32][33];
    const int tx = threadIdx.x;
    const int ty = threadIdx.y;
    const bool is_qkv = (blockIdx.x < 96);
    const float* in = is_qkv ? Wqkv : Wout;
    __nv_bfloat16* hiT = is_qkv ? g_wqkv_h : g_wout_h;
    __nv_bfloat16* loT = is_qkv ? g_wqkv_l : g_wout_l;
    const int N = is_qkv ? QKV_N : Dc;
    const int n0 = (is_qkv ? blockIdx.x : (blockIdx.x - 96)) * 32;
    const int k0 = blockIdx.y * 32;
    const int K = Dc;

    #pragma unroll
    for (int i = 0; i < 4; i++) {
        int row = ty + i * 8;
        t[row][tx] = in[(size_t)(k0 + row) * N + n0 + tx];
    }
    __syncthreads();
    #pragma unroll
    for (int i = 0; i < 4; i++) {
        int row = ty + i * 8;
        float v = t[tx][row];
        __nv_bfloat16 h = __float2bfloat16(v);
        size_t o = (size_t)(n0 + row) * K + k0 + tx;
        hiT[o] = h;
        loT[o] = __float2bfloat16(v - __bfloat162float(h));
    }
}

// ---------------------------------------------------------------------------
extern "C" void kernel_launch(void* const* d_in, const int* in_sizes, int n_in,
                              void* d_out, int out_size)
{
    const float* x    = (const float*)d_in[0];
    const int*   pos  = (const int*)  d_in[1];
    const float* Wqkv = (const float*)d_in[2];
    const float* Wout = (const float*)d_in[3];
    float* out = (float*)d_out;

    float *qkv_ptr = nullptr;
    __nv_bfloat16 *xh, *xl, *wqh, *wql, *woh, *wol, *ah, *al;
    cudaGetSymbolAddress((void**)&qkv_ptr,  g_qkv);
    cudaGetSymbolAddress((void**)&xh,  g_xh);
    cudaGetSymbolAddress((void**)&xl,  g_xl);
    cudaGetSymbolAddress((void**)&wqh, g_wqkv_h);
    cudaGetSymbolAddress((void**)&wql, g_wqkv_l);
    cudaGetSymbolAddress((void**)&woh, g_wout_h);
    cudaGetSymbolAddress((void**)&wol, g_wout_l);
    cudaGetSymbolAddress((void**)&ah,  g_ah);
    cudaGetSymbolAddress((void**)&al,  g_al);

    static bool attr_set = false;
    if (!attr_set) {
        cudaFuncSetAttribute(gemm_mma_kernel,
                             cudaFuncAttributeMaxDynamicSharedMemorySize, MMA_GEMM_SMEM);
        cudaFuncSetAttribute(attn_mma_kernel,
                             cudaFuncAttributeMaxDynamicSharedMemorySize, ATTN_SMEM);
        attr_set = true;
    }

    // 0) Input split (x) + both weight transposes (single launch)
    {
        int n4 = BT * Dc / 4;
        split_kernel<<<(n4 + 255) / 256, 256>>>(
            (const float4*)x, (__nv_bfloat162*)xh, (__nv_bfloat162*)xl, n4);
    }
    {
        dim3 grid(96 + 32, 32);
        transpose_split_both_kernel<<<grid, dim3(32, 8)>>>(Wqkv, Wout);
    }

    // 1) QKV projection on HMMA: 128x128 tiles, 2 CTAs/SM
    {
        dim3 grid(QKV_N / 128, BT / 128);
        gemm_mma_kernel<<<grid, 256, MMA_GEMM_SMEM>>>(
            xh, xl, wqh, wql, qkv_ptr, QKV_N, Dc);
    }

    // 2) Pre-convert Q/K/V to bf16 hi/lo attention layouts (V transposed)
    {
        dim3 grid(Tc / 64, Hc, Bc);
        preconvert_kernel<<<grid, 256>>>(qkv_ptr);
    }

    // 3) Attention on HMMA (KV tile 128, LPT order, fused output split)
    {
        dim3 grid(Tc / 128, Hc, Bc);
        attn_mma_kernel<<<grid, 256, ATTN_SMEM>>>(pos, ah, al);
    }

    // 4) Out projection on HMMA: 128x128 tiles, 2 CTAs/SM
    {
        dim3 grid(Dc / 128, BT / 128);
        gemm_mma_kernel<<<grid, 256, MMA_GEMM_SMEM>>>(
            ah, al, woh, wol, out, Dc, Dc);
    }
}

// round 16
// speedup vs baseline: 1.0984x; 1.0243x over previous
#include <cuda_runtime.h>
#include <cuda_bf16.h>
#include <cstdint>
#include <math.h>

// Problem constants (fixed by the dataset)
#define Bc 4
#define Tc 2048
#define Dc 1024
#define Hc 16
#define HDc 64
#define BT (Bc*Tc)        // 8192
#define QKV_N (3*Dc)      // 3072

// ---------------------------------------------------------------------------
// Global scratch (no cudaMalloc allowed)
// ---------------------------------------------------------------------------
__device__ __nv_bfloat16 g_xh[BT * Dc];
__device__ __nv_bfloat16 g_xl[BT * Dc];
__device__ __nv_bfloat16 g_wqkv_h[QKV_N * Dc];  // Wqkv^T hi/lo, [3072,1024]
__device__ __nv_bfloat16 g_wqkv_l[QKV_N * Dc];
__device__ __nv_bfloat16 g_wout_h[Dc * Dc];
__device__ __nv_bfloat16 g_wout_l[Dc * Dc];
__device__ __nv_bfloat16 g_ah[BT * Dc];    // attention out hi/lo (A of out proj)
__device__ __nv_bfloat16 g_al[BT * Dc];
// Attention operands (written directly by the qkv GEMM epilogue):
__device__ __nv_bfloat16 g_qh[Bc * Hc * Tc * HDc];   // [B][H][T][64] scaled
__device__ __nv_bfloat16 g_ql[Bc * Hc * Tc * HDc];
__device__ __nv_bfloat16 g_kh[Bc * Hc * Tc * HDc];   // [B][H][T][64]
__device__ __nv_bfloat16 g_kl[Bc * Hc * Tc * HDc];
__device__ __nv_bfloat16 g_vh[Bc * Hc * HDc * Tc];   // [B][H][64][T] transposed
__device__ __nv_bfloat16 g_vl[Bc * Hc * HDc * Tc];

// ---------------------------------------------------------------------------
// PTX helpers (base compute_103: mma.sync + ldmatrix + cp.async)
// ---------------------------------------------------------------------------
__device__ __forceinline__ uint32_t smem_to_u32(const void* p) {
    uint32_t a;
    asm("{ .reg .u64 t; cvta.to.shared.u64 t, %1; cvt.u32.u64 %0, t; }" : "=r"(a) : "l"(p));
    return a;
}

#define CP_ASYNC_16(dst, src) \
    asm volatile("cp.async.cg.shared.global [%0], [%1], 16;" :: "r"(dst), "l"(src))
#define CP_ASYNC_COMMIT() \
    asm volatile("cp.async.commit_group;" ::: "memory")
#define CP_ASYNC_WAIT(n) \
    asm volatile("cp.async.wait_group %0;" :: "n"(n) : "memory")

#define LDSM_X4(r0, r1, r2, r3, addr) \
    asm volatile("ldmatrix.sync.aligned.m8n8.x4.shared.b16 {%0,%1,%2,%3}, [%4];" \
        : "=r"(r0), "=r"(r1), "=r"(r2), "=r"(r3) : "r"(addr))

#define MMA_BF16(d, a, b) \
    asm volatile("mma.sync.aligned.m16n8k16.row.col.f32.bf16.bf16.f32 " \
        "{%0,%1,%2,%3}, {%4,%5,%6,%7}, {%8,%9}, {%0,%1,%2,%3};" \
        : "+f"((d)[0]), "+f"((d)[1]), "+f"((d)[2]), "+f"((d)[3]) \
        : "r"((a)[0]), "r"((a)[1]), "r"((a)[2]), "r"((a)[3]), \
          "r"((b)[0]), "r"((b)[1]))

#define MMA_AB(d, a, b0v, b1v) \
    asm volatile("mma.sync.aligned.m16n8k16.row.col.f32.bf16.bf16.f32 " \
        "{%0,%1,%2,%3}, {%4,%5,%6,%7}, {%8,%9}, {%0,%1,%2,%3};" \
        : "+f"((d)[0]), "+f"((d)[1]), "+f"((d)[2]), "+f"((d)[3]) \
        : "r"((a)[0]), "r"((a)[1]), "r"((a)[2]), "r"((a)[3]), \
          "r"(b0v), "r"(b1v))

__device__ __forceinline__ void split2(float a, float b, uint32_t& hi, uint32_t& lo) {
    __nv_bfloat16 ha = __float2bfloat16(a), hb = __float2bfloat16(b);
    __nv_bfloat162 hh = __halves2bfloat162(ha, hb);
    __nv_bfloat162 ll = __halves2bfloat162(
        __float2bfloat16(a - __bfloat162float(ha)),
        __float2bfloat16(b - __bfloat162float(hb)));
    hi = *(uint32_t*)&hh;
    lo = *(uint32_t*)&ll;
}

// ---------------------------------------------------------------------------
// bf16-split GEMM via mma.sync — proven config: 128x128 tile, 2 CTAs/SM,
// BK=32, double-buffered cp.async.
// MODE 0: plain fp32 C output (out projection).
// MODE 1: qkv fused epilogue — writes Q/K/V bf16 hi/lo attention layouts
//         directly (Q scaled 0.125, V transposed). C is unused.
// ---------------------------------------------------------------------------
#define BKc 32
#define ROWB 80
#define TILE_SB (128 * ROWB)
#define STAGE_SB (4 * TILE_SB)
#define MMA_GEMM_SMEM (2 * STAGE_SB)

template<int MODE>
__global__ __launch_bounds__(256, 2) void gemm_mma_kernel(
    const __nv_bfloat16* __restrict__ Ah, const __nv_bfloat16* __restrict__ Al,
    const __nv_bfloat16* __restrict__ Bh, const __nv_bfloat16* __restrict__ Bl,
    float* __restrict__ C, int N, int K)
{
    extern __shared__ __align__(128) char smem[];
    const uint32_t sb = smem_to_u32(smem);
    const int tid  = threadIdx.x;
    const int lane = tid & 31;
    const int wid  = tid >> 5;
    const int wm   = wid & 1;
    const int wn   = wid >> 1;
    const int m0 = blockIdx.y * 128;
    const int n0 = blockIdx.x * 128;
    const int nchunk = K / BKc;

    float acc[4][4][4];
    #pragma unroll
    for (int i = 0; i < 4; i++)
        #pragma unroll
        for (int j = 0; j < 4; j++)
            #pragma unroll
            for (int r = 0; r < 4; r++) acc[i][j][r] = 0.f;

    const __nv_bfloat16* srcs[4] = {Ah, Al, Bh, Bl};

    auto load_chunk = [&](int c, int buf) {
        #pragma unroll
        for (int t = 0; t < 4; t++) {
            const __nv_bfloat16* src = srcs[t];
            const int rbase = (t < 2) ? m0 : n0;
            #pragma unroll
            for (int i = 0; i < 2; i++) {
                int idx = tid + i * 256;
                int r = idx >> 2;
                int q = idx & 3;
                uint32_t dst = sb + buf * STAGE_SB + t * TILE_SB + r * ROWB + q * 16;
                const void* g = src + (size_t)(rbase + r) * K + c * BKc + q * 8;
                CP_ASYNC_16(dst, g);
            }
        }
        CP_ASYNC_COMMIT();
    };

    load_chunk(0, 0);

    for (int c = 0; c < nchunk; c++) {
        const int buf = c & 1;
        if (c + 1 < nchunk) {
            load_chunk(c + 1, buf ^ 1);
            CP_ASYNC_WAIT(1);
        } else {
            CP_ASYNC_WAIT(0);
        }
        __syncthreads();

        const uint32_t a_base = sb + buf * STAGE_SB;
        const uint32_t b_base = a_base + 2 * TILE_SB;

        #pragma unroll
        for (int ks = 0; ks < 2; ks++) {
            uint32_t ah[4][4], al[4][4];
            #pragma unroll
            for (int mf = 0; mf < 4; mf++) {
                int row = wm * 64 + mf * 16 + (lane & 15);
                uint32_t col = ks * 32 + ((lane >> 4) * 16);
                uint32_t addr = a_base + row * ROWB + col;
                LDSM_X4(ah[mf][0], ah[mf][1], ah[mf][2], ah[mf][3], addr);
                LDSM_X4(al[mf][0], al[mf][1], al[mf][2], al[mf][3], addr + TILE_SB);
            }
            uint32_t bh[4][2], bl[4][2];
            #pragma unroll
            for (int p = 0; p < 2; p++) {
                int row = wn * 32 + p * 16 + ((lane >> 4) << 3) + (lane & 7);
                uint32_t col = ks * 32 + (((lane >> 3) & 1) * 16);
                uint32_t addr = b_base + row * ROWB + col;
                LDSM_X4(bh[2*p][0], bh[2*p][1], bh[2*p+1][0], bh[2*p+1][1], addr);
                LDSM_X4(bl[2*p][0], bl[2*p][1], bl[2*p+1][0], bl[2*p+1][1], addr + TILE_SB);
            }
            #pragma unroll
            for (int mf = 0; mf < 4; mf++)
                #pragma unroll
                for (int nf = 0; nf < 4; nf++)
                    MMA_BF16(acc[mf][nf], ah[mf], bh[nf]);
            #pragma unroll
            for (int mf = 0; mf < 4; mf++)
                #pragma unroll
                for (int nf = 0; nf < 4; nf++)
                    MMA_BF16(acc[mf][nf], ah[mf], bl[nf]);
            #pragma unroll
            for (int mf = 0; mf < 4; mf++)
                #pragma unroll
                for (int nf = 0; nf < 4; nf++)
                    MMA_BF16(acc[mf][nf], al[mf], bh[nf]);
        }
        __syncthreads();
    }

    if (MODE == 0) {
        // Plain fp32 output
        #pragma unroll
        for (int mf = 0; mf < 4; mf++) {
            #pragma unroll
            for (int nf = 0; nf < 4; nf++) {
                int row = m0 + wm * 64 + mf * 16 + (lane >> 2);
                int col = n0 + wn * 32 + nf * 8 + (lane & 3) * 2;
                *(float2*)&C[(size_t)row * N + col] =
                    make_float2(acc[mf][nf][0], acc[mf][nf][1]);
                *(float2*)&C[(size_t)(row + 8) * N + col] =
                    make_float2(acc[mf][nf][2], acc[mf][nf][3]);
            }
        }
    } else {
        // Fused qkv epilogue: region uniform per CTA (n0 multiple of 128)
        const int region = n0 >> 10;            // 0=Q, 1=K, 2=V
        #pragma unroll
        for (int mf = 0; mf < 4; mf++) {
            #pragma unroll
            for (int nf = 0; nf < 4; nf++) {
                const int row0 = m0 + wm * 64 + mf * 16 + (lane >> 2);
                const int colg = n0 + wn * 32 + nf * 8 + (lane & 3) * 2;
                const int d  = colg & 1023;
                const int hh = d >> 6;
                const int hd = d & 63;
                #pragma unroll
                for (int half = 0; half < 2; half++) {
                    const int row = row0 + half * 8;
                    const int bb = row >> 11;       // batch
                    const int t  = row & 2047;      // token
                    float v0 = acc[mf][nf][2*half];
                    float v1 = acc[mf][nf][2*half+1];
                    if (region == 0) {
                        uint32_t hi, lo;
                        split2(v0 * 0.125f, v1 * 0.125f, hi, lo);
                        size_t o = (((size_t)bb * Hc + hh) * Tc + t) * HDc + hd;
                        *(uint32_t*)&g_qh[o] = hi;
                        *(uint32_t*)&g_ql[o] = lo;
                    } else if (region == 1) {
                        uint32_t hi, lo;
                        split2(v0, v1, hi, lo);
                        size_t o = (((size_t)bb * Hc + hh) * Tc + t) * HDc + hd;
                        *(uint32_t*)&g_kh[o] = hi;
                        *(uint32_t*)&g_kl[o] = lo;
                    } else {
                        // V transposed: [b][h][hd][t]
                        __nv_bfloat16 h0 = __float2bfloat16(v0);
                        __nv_bfloat16 h1 = __float2bfloat16(v1);
                        __nv_bfloat16 l0 = __float2bfloat16(v0 - __bfloat162float(h0));
                        __nv_bfloat16 l1 = __float2bfloat16(v1 - __bfloat162float(h1));
                        size_t ob = (((size_t)bb * Hc + hh) * HDc + hd) * Tc + t;
                        g_vh[ob] = h0;       g_vl[ob] = l0;
                        g_vh[ob + Tc] = h1;  g_vl[ob + Tc] = l1;
                    }
                }
            }
        }
    }
}

// ---------------------------------------------------------------------------
// HMMA flash attention, KV tile = 128 tokens, cp.async double-buffered,
// LPT q-tile order, fused bf16 hi/lo output split.
// ---------------------------------------------------------------------------
#define TKV 128
#define QHB 0
#define QLB 18432
#define STG0 36864
#define KL_OFF 18432
#define VH_OFF 36864
#define VL_OFF 54272
#define STG_SZ 71680
#define VROWB 272
#define POSB (STG0 + 2*STG_SZ)          // 180224
#define ATTN_SMEM (POSB + 2*TKV*4)      // 181248

__global__ __launch_bounds__(256) void attn_mma_kernel(
    const int* __restrict__ pos,
    __nv_bfloat16* __restrict__ outh,
    __nv_bfloat16* __restrict__ outl)
{
    extern __shared__ __align__(128) char smem[];
    const uint32_t sb = smem_to_u32(smem);
    int* spos = (int*)(smem + POSB);

    const int tid  = threadIdx.x;
    const int lane = tid & 31;
    const int wid  = tid >> 5;

    // Longest blocks (largest q0 => most KV tiles) first
    const int q0  = ((int)gridDim.x - 1 - (int)blockIdx.x) * 128;
    const int h   = blockIdx.y;
    const int b   = blockIdx.z;
    const int bt0 = b * Tc + q0;
    const int bT  = b * Tc;
    const size_t bhT = ((size_t)b * Hc + h) * Tc;
    const size_t bhV = ((size_t)b * Hc + h) * HDc;

    // Q hi/lo into smem (coalesced 16B)
    for (int i = tid; i < 128 * 8; i += 256) {
        int r = i >> 3, q = i & 7;
        *(uint4*)(smem + QHB + r * 144 + q * 16) =
            *(const uint4*)(g_qh + (bhT + q0 + r) * HDc + q * 8);
        *(uint4*)(smem + QLB + r * 144 + q * 16) =
            *(const uint4*)(g_ql + (bhT + q0 + r) * HDc + q * 8);
    }
    const int pq0 = pos[bt0 + wid * 16 + (lane >> 2)];
    const int pq1 = pos[bt0 + wid * 16 + (lane >> 2) + 8];
    const int pqmax = pos[bt0 + 127];

    auto kv_prefetch = [&](int it, int s) {
        const uint32_t st = sb + STG0 + s * STG_SZ;
        const int k0 = it * TKV;
        #pragma unroll
        for (int i = 0; i < 4; i++) {
            int idx = tid + i * 256;
            int j = idx >> 3, q = idx & 7;
            uint32_t d = st + j * 144 + q * 16;
            CP_ASYNC_16(d,          g_kh + (bhT + k0 + j) * HDc + q * 8);
            CP_ASYNC_16(d + KL_OFF, g_kl + (bhT + k0 + j) * HDc + q * 8);
        }
        #pragma unroll
        for (int i = 0; i < 4; i++) {
            int idx = tid + i * 256;
            int j = idx >> 4, q = idx & 15;
            uint32_t d = st + VH_OFF + j * VROWB + q * 16;
            CP_ASYNC_16(d,                     g_vh + (bhV + j) * Tc + k0 + q * 8);
            CP_ASYNC_16(d + (VL_OFF - VH_OFF), g_vl + (bhV + j) * Tc + k0 + q * 8);
        }
        if (tid < TKV) spos[s * TKV + tid] = pos[bT + k0 + tid];
        CP_ASYNC_COMMIT();
    };

    kv_prefetch(0, 0);
    int nt = 1;
    while (nt < Tc / TKV && pos[bT + nt * TKV] <= pqmax) nt++;

    __syncthreads();

    uint32_t qh[4][4], ql[4][4];
    #pragma unroll
    for (int ks = 0; ks < 4; ks++) {
        uint32_t addr = sb + QHB + (wid * 16 + (lane & 15)) * 144
                      + ks * 32 + (lane >> 4) * 16;
        LDSM_X4(qh[ks][0], qh[ks][1], qh[ks][2], qh[ks][3], addr);
        LDSM_X4(ql[ks][0], ql[ks][1], ql[ks][2], ql[ks][3], addr + (QLB - QHB));
    }

    float m0 = -1e30f, m1 = -1e30f, l0 = 0.f, l1 = 0.f;
    float oacc[8][4];
    #pragma unroll
    for (int nf = 0; nf < 8; nf++)
        #pragma unroll
        for (int r = 0; r < 4; r++) oacc[nf][r] = 0.f;

    for (int it = 0; it < nt; it++) {
        const int buf = it & 1;
        if (it + 1 < nt) {
            kv_prefetch(it + 1, buf ^ 1);
            CP_ASYNC_WAIT(1);
        } else {
            CP_ASYNC_WAIT(0);
        }
        __syncthreads();

        const uint32_t st = sb + STG0 + buf * STG_SZ;

        float sacc[16][4];
        #pragma unroll
        for (int nf = 0; nf < 16; nf++)
            #pragma unroll
            for (int r = 0; r < 4; r++) sacc[nf][r] = 0.f;

        #pragma unroll
        for (int ks = 0; ks < 4; ks++) {
            #pragma unroll
            for (int p = 0; p < 8; p++) {
                uint32_t row = p * 16 + ((lane >> 4) << 3) + (lane & 7);
                uint32_t addr = st + row * 144 + ks * 32 + (((lane >> 3) & 1) * 16);
                uint32_t h0, h1, h2, h3, lo0, lo1, lo2, lo3;
                LDSM_X4(h0, h1, h2, h3, addr);
                LDSM_X4(lo0, lo1, lo2, lo3, addr + KL_OFF);
                MMA_AB(sacc[2*p],   qh[ks], h0, h1);
                MMA_AB(sacc[2*p],   qh[ks], lo0, lo1);
                MMA_AB(sacc[2*p],   ql[ks], h0, h1);
                MMA_AB(sacc[2*p+1], qh[ks], h2, h3);
                MMA_AB(sacc[2*p+1], qh[ks], lo2, lo3);
                MMA_AB(sacc[2*p+1], ql[ks], h2, h3);
            }
        }

        const int* sp = spos + buf * TKV;
        float mx0 = -1e30f, mx1 = -1e30f;
        #pragma unroll
        for (int nf = 0; nf < 16; nf++) {
            int jc = nf * 8 + (lane & 3) * 2;
            int p0 = sp[jc], p1 = sp[jc + 1];
            if (p0 > pq0) sacc[nf][0] = -1e30f;
            if (p1 > pq0) sacc[nf][1] = -1e30f;
            if (p0 > pq1) sacc[nf][2] = -1e30f;
            if (p1 > pq1) sacc[nf][3] = -1e30f;
            mx0 = fmaxf(mx0, fmaxf(sacc[nf][0], sacc[nf][1]));
            mx1 = fmaxf(mx1, fmaxf(sacc[nf][2], sacc[nf][3]));
        }
        mx0 = fmaxf(mx0, __shfl_xor_sync(0xffffffffu, mx0, 1));
        mx0 = fmaxf(mx0, __shfl_xor_sync(0xffffffffu, mx0, 2));
        mx1 = fmaxf(mx1, __shfl_xor_sync(0xffffffffu, mx1, 1));
        mx1 = fmaxf(mx1, __shfl_xor_sync(0xffffffffu, mx1, 2));

        float mn0 = fmaxf(m0, mx0), mn1 = fmaxf(m1, mx1);
        float al0 = __expf(m0 - mn0), al1 = __expf(m1 - mn1);
        float ps0 = 0.f, ps1 = 0.f;
        #pragma unroll
        for (int nf = 0; nf < 16; nf++) {
            sacc[nf][0] = __expf(sacc[nf][0] - mn0); ps0 += sacc[nf][0];
            sacc[nf][1] = __expf(sacc[nf][1] - mn0); ps0 += sacc[nf][1];
            sacc[nf][2] = __expf(sacc[nf][2] - mn1); ps1 += sacc[nf][2];
            sacc[nf][3] = __expf(sacc[nf][3] - mn1); ps1 += sacc[nf][3];
        }
        ps0 += __shfl_xor_sync(0xffffffffu, ps0, 1);
        ps0 += __shfl_xor_sync(0xffffffffu, ps0, 2);
        ps1 += __shfl_xor_sync(0xffffffffu, ps1, 1);
        ps1 += __shfl_xor_sync(0xffffffffu, ps1, 2);
        l0 = l0 * al0 + ps0;  m0 = mn0;
        l1 = l1 * al1 + ps1;  m1 = mn1;
        #pragma unroll
        for (int nf = 0; nf < 8; nf++) {
            oacc[nf][0] *= al0; oacc[nf][1] *= al0;
            oacc[nf][2] *= al1; oacc[nf][3] *= al1;
        }

        #pragma unroll
        for (int ksp = 0; ksp < 8; ksp++) {
            uint32_t ph[4], pl[4];
            split2(sacc[2*ksp][0],   sacc[2*ksp][1],   ph[0], pl[0]);
            split2(sacc[2*ksp][2],   sacc[2*ksp][3],   ph[1], pl[1]);
            split2(sacc[2*ksp+1][0], sacc[2*ksp+1][1], ph[2], pl[2]);
            split2(sacc[2*ksp+1][2], sacc[2*ksp+1][3], ph[3], pl[3]);
            #pragma unroll
            for (int p = 0; p < 4; p++) {
                uint32_t row = p * 16 + ((lane >> 4) << 3) + (lane & 7);
                uint32_t addr = st + VH_OFF + row * VROWB
                              + ksp * 32 + (((lane >> 3) & 1) * 16);
                uint32_t v0, v1, v2, v3, w0, w1, w2, w3;
                LDSM_X4(v0, v1, v2, v3, addr);
                LDSM_X4(w0, w1, w2, w3, addr + (VL_OFF - VH_OFF));
                MMA_AB(oacc[2*p],   ph, v0, v1);
                MMA_AB(oacc[2*p],   ph, w0, w1);
                MMA_AB(oacc[2*p],   pl, v0, v1);
                MMA_AB(oacc[2*p+1], ph, v2, v3);
                MMA_AB(oacc[2*p+1], ph, w2, w3);
                MMA_AB(oacc[2*p+1], pl, v2, v3);
            }
        }
        __syncthreads();
    }

    const float inv0 = 1.0f / l0;
    const float inv1 = 1.0f / l1;
    const int r0 = bt0 + wid * 16 + (lane >> 2);
    const int r1 = r0 + 8;
    #pragma unroll
    for (int nf = 0; nf < 8; nf++) {
        int col = h * HDc + nf * 8 + (lane & 3) * 2;
        uint32_t hi, lo;
        split2(oacc[nf][0] * inv0, oacc[nf][1] * inv0, hi, lo);
        *(uint32_t*)&outh[(size_t)r0 * Dc + col] = hi;
        *(uint32_t*)&outl[(size_t)r0 * Dc + col] = lo;
        split2(oacc[nf][2] * inv1, oacc[nf][3] * inv1, hi, lo);
        *(uint32_t*)&outh[(size_t)r1 * Dc + col] = hi;
        *(uint32_t*)&outl[(size_t)r1 * Dc + col] = lo;
    }
}

// ---------------------------------------------------------------------------
// fp32 -> bf16 hi/lo split (vectorized x4)
// ---------------------------------------------------------------------------
__global__ __launch_bounds__(256) void split_kernel(
    const float4* __restrict__ in, __nv_bfloat162* __restrict__ hi,
    __nv_bfloat162* __restrict__ lo, int n4)
{
    int i = blockIdx.x * blockDim.x + threadIdx.x;
    if (i >= n4) return;
    float4 v = in[i];
    __nv_bfloat16 h0 = __float2bfloat16(v.x);
    __nv_bfloat16 h1 = __float2bfloat16(v.y);
    __nv_bfloat16 h2 = __float2bfloat16(v.z);
    __nv_bfloat16 h3 = __float2bfloat16(v.w);
    hi[2*i]   = __halves2bfloat162(h0, h1);
    hi[2*i+1] = __halves2bfloat162(h2, h3);
    lo[2*i]   = __halves2bfloat162(__float2bfloat16(v.x - __bfloat162float(h0)),
                                   __float2bfloat16(v.y - __bfloat162float(h1)));
    lo[2*i+1] = __halves2bfloat162(__float2bfloat16(v.z - __bfloat162float(h2)),
                                   __float2bfloat16(v.w - __bfloat162float(h3)));
}

// ---------------------------------------------------------------------------
// Both weight transposes in ONE launch: W [K,N] fp32 -> W^T [N,K] bf16 hi/lo.
// ---------------------------------------------------------------------------
__global__ __launch_bounds__(256) void transpose_split_both_kernel(
    const float* __restrict__ Wqkv, const float* __restrict__ Wout)
{
    __shared__ float t[32][33];
    const int tx = threadIdx.x;
    const int ty = threadIdx.y;
    const bool is_qkv = (blockIdx.x < 96);
    const float* in = is_qkv ? Wqkv : Wout;
    __nv_bfloat16* hiT = is_qkv ? g_wqkv_h : g_wout_h;
    __nv_bfloat16* loT = is_qkv ? g_wqkv_l : g_wout_l;
    const int N = is_qkv ? QKV_N : Dc;
    const int n0 = (is_qkv ? blockIdx.x : (blockIdx.x - 96)) * 32;
    const int k0 = blockIdx.y * 32;
    const int K = Dc;

    #pragma unroll
    for (int i = 0; i < 4; i++) {
        int row = ty + i * 8;
        t[row][tx] = in[(size_t)(k0 + row) * N + n0 + tx];
    }
    __syncthreads();
    #pragma unroll
    for (int i = 0; i < 4; i++) {
        int row = ty + i * 8;
        float v = t[tx][row];
        __nv_bfloat16 h = __float2bfloat16(v);
        size_t o = (size_t)(n0 + row) * K + k0 + tx;
        hiT[o] = h;
        loT[o] = __float2bfloat16(v - __bfloat162float(h));
    }
}

// ---------------------------------------------------------------------------
extern "C" void kernel_launch(void* const* d_in, const int* in_sizes, int n_in,
                              void* d_out, int out_size)
{
    const float* x    = (const float*)d_in[0];
    const int*   pos  = (const int*)  d_in[1];
    const float* Wqkv = (const float*)d_in[2];
    const float* Wout = (const float*)d_in[3];
    float* out = (float*)d_out;

    __nv_bfloat16 *xh, *xl, *wqh, *wql, *woh, *wol, *ah, *al;
    cudaGetSymbolAddress((void**)&xh,  g_xh);
    cudaGetSymbolAddress((void**)&xl,  g_xl);
    cudaGetSymbolAddress((void**)&wqh, g_wqkv_h);
    cudaGetSymbolAddress((void**)&wql, g_wqkv_l);
    cudaGetSymbolAddress((void**)&woh, g_wout_h);
    cudaGetSymbolAddress((void**)&wol, g_wout_l);
    cudaGetSymbolAddress((void**)&ah,  g_ah);
    cudaGetSymbolAddress((void**)&al,  g_al);

    static bool attr_set = false;
    if (!attr_set) {
        cudaFuncSetAttribute(gemm_mma_kernel<0>,
                             cudaFuncAttributeMaxDynamicSharedMemorySize, MMA_GEMM_SMEM);
        cudaFuncSetAttribute(gemm_mma_kernel<1>,
                             cudaFuncAttributeMaxDynamicSharedMemorySize, MMA_GEMM_SMEM);
        cudaFuncSetAttribute(attn_mma_kernel,
                             cudaFuncAttributeMaxDynamicSharedMemorySize, ATTN_SMEM);
        attr_set = true;
    }

    // 0) Input split (x) + both weight transposes (single launch)
    {
        int n4 = BT * Dc / 4;
        split_kernel<<<(n4 + 255) / 256, 256>>>(
            (const float4*)x, (__nv_bfloat162*)xh, (__nv_bfloat162*)xl, n4);
    }
    {
        dim3 grid(96 + 32, 32);
        transpose_split_both_kernel<<<grid, dim3(32, 8)>>>(Wqkv, Wout);
    }

    // 1) QKV projection on HMMA with FUSED attention-layout epilogue
    //    (writes g_qh/ql, g_kh/kl, g_vh/vl directly; no fp32 intermediate)
    {
        dim3 grid(QKV_N / 128, BT / 128);
        gemm_mma_kernel<1><<<grid, 256, MMA_GEMM_SMEM>>>(
            xh, xl, wqh, wql, nullptr, QKV_N, Dc);
    }

    // 2) Attention on HMMA (KV tile 128, LPT order, fused output split)
    {
        dim3 grid(Tc / 128, Hc, Bc);
        attn_mma_kernel<<<grid, 256, ATTN_SMEM>>>(pos, ah, al);
    }

    // 3) Out projection on HMMA: plain fp32 epilogue
    {
        dim3 grid(Dc / 128, BT / 128);
        gemm_mma_kernel<0><<<grid, 256, MMA_GEMM_SMEM>>>(
            ah, al, woh, wol, out, Dc, Dc);
    }
}